// round 12
// baseline (speedup 1.0000x reference)
#include <cuda_runtime.h>
#include <cuda_bf16.h>
#include <math.h>

typedef unsigned int u32;

// Problem constants
constexpr int BB = 2, RR = 64, CC = 2048, EE = 128, HH = 4, DH = 32;
constexpr long long MROWS = (long long)BB * RR * CC;        // 262144
constexpr int NTILES = (int)(MROWS / 64);                    // 4096
constexpr int NKV = BB * RR * HH;                            // 512
constexpr int NBR = BB * RR;                                 // 128

// Scratch (device globals — no runtime allocation)
__device__ float g_part[(long long)NTILES * HH * DH * DH];   // 67 MB KtV partials
__device__ float g_ksum_part[NTILES * EE];                   // 2 MB
__device__ float g_ksum_final[NKV * DH];                     // 64 KB
// Pre-swizzled bf16 weight images: [matrix 0..3][hi 2048 | lo 2048] uint4 chunks
__device__ uint4 g_wimg[4 * 4096];
// Pre-swizzled bf16 KtV images: per br: [hi 512 | lo 512] uint4 (h,d,cc)
__device__ uint4 g_ktvimg[NBR * 1024];

// ---------------------------------------------------------------------------
// helpers
// ---------------------------------------------------------------------------
__device__ __forceinline__ void ldsm4(u32 a, u32& r0, u32& r1, u32& r2, u32& r3) {
    asm volatile("ldmatrix.sync.aligned.m8n8.x4.shared.b16 {%0,%1,%2,%3},[%4];"
                 : "=r"(r0), "=r"(r1), "=r"(r2), "=r"(r3) : "r"(a));
}
__device__ __forceinline__ void ldsm4t(u32 a, u32& r0, u32& r1, u32& r2, u32& r3) {
    asm volatile("ldmatrix.sync.aligned.m8n8.x4.trans.shared.b16 {%0,%1,%2,%3},[%4];"
                 : "=r"(r0), "=r"(r1), "=r"(r2), "=r"(r3) : "r"(a));
}
__device__ __forceinline__ void mma_bf16(float c[4], const u32 a[4], u32 b0, u32 b1) {
    asm volatile(
        "mma.sync.aligned.m16n8k16.row.col.f32.bf16.bf16.f32 "
        "{%0,%1,%2,%3},{%4,%5,%6,%7},{%8,%9},{%0,%1,%2,%3};"
        : "+f"(c[0]), "+f"(c[1]), "+f"(c[2]), "+f"(c[3])
        : "r"(a[0]), "r"(a[1]), "r"(a[2]), "r"(a[3]), "r"(b0), "r"(b1));
}

__device__ __forceinline__ void cvt2(float a, float b, u32& hi, u32& lo) {
    __nv_bfloat16 ah16 = __float2bfloat16_rn(a);
    __nv_bfloat16 bh16 = __float2bfloat16_rn(b);
    float ar = a - __bfloat162float(ah16);
    float br = b - __bfloat162float(bh16);
    __nv_bfloat162 hp = __halves2bfloat162(ah16, bh16);
    __nv_bfloat162 lp = __floats2bfloat162_rn(ar, br);
    hi = *(u32*)&hp;
    lo = *(u32*)&lp;
}

__device__ __forceinline__ void cvt8(const float* f, uint4& hi, uint4& lo) {
    u32 h[4];
    u32 l[4];
#pragma unroll
    for (int i = 0; i < 4; ++i) cvt2(f[2 * i], f[2 * i + 1], h[i], l[i]);
    hi = make_uint4(h[0], h[1], h[2], h[3]);
    lo = make_uint4(l[0], l[1], l[2], l[3]);
}

__device__ __forceinline__ float elu1(float x) {
    return (x > 0.f) ? (x + 1.f) : expf(x);
}

// ---- smem layout (bytes), fused kv/KtV kernel (R10-proven, unchanged) ----
constexpr int SOFF_XHI = 0;
constexpr int SOFF_XLO = 16384;
constexpr int SOFF_W   = 32768;
constexpr int SOFF_VHI = 32768;
constexpr int SOFF_VLO = 49152;
constexpr int SOFF_KHI = 65536;
constexpr int SOFF_KLO = 81920;
constexpr int SOFF_SCR = 65536;
constexpr int SOFF_KS2 = 98304;
constexpr int SMEM_FUSED = 98304 + 1024;   // 99328

// ---- tout smem layout (M=128): A [0,64K), W [64K,128K), KtV [128K,192K) ----
constexpr int T_AHI = 0;
constexpr int T_ALO = 32768;
constexpr int T_WHI = 65536;
constexpr int T_WLO = 98304;
constexpr int T_KHI = 131072;               // 128 rows x 256B, sparse chunks
constexpr int T_KLO = 163840;
constexpr int SMEM_TOUT = 196608;           // 192 KB, 1 CTA/SM

// ---------------------------------------------------------------------------
// Kernel 0: precompute bf16 hi/lo swizzled images of the 4 weight matrices.
// ---------------------------------------------------------------------------
__global__ __launch_bounds__(256)
void prep_w_kernel(const float* __restrict__ Wq, const float* __restrict__ Wk,
                   const float* __restrict__ Wv, const float* __restrict__ Wo)
{
    const float* Ws[4] = {Wq, Wk, Wv, Wo};
    const float4* W = (const float4*)Ws[blockIdx.x];
    uint4* dst = g_wimg + blockIdx.x * 4096;
    const int tid = threadIdx.x;
#pragma unroll
    for (int it = 0; it < 8; ++it) {
        int idx = tid + it * 256;            // 2048 chunks
        int row = idx >> 4;
        int ch = idx & 15;
        float4 f0 = W[row * 32 + ch * 2];
        float4 f1 = W[row * 32 + ch * 2 + 1];
        float f[8] = {f0.x, f0.y, f0.z, f0.w, f1.x, f1.y, f1.z, f1.w};
        uint4 hi, lo;
        cvt8(f, hi, lo);
        int c = row * 16 + (ch ^ (row & 7));
        dst[c] = hi;
        dst[2048 + c] = lo;
    }
}

// ---------------------------------------------------------------------------
// X tile load (64 rows) for the fused kernel.
// ---------------------------------------------------------------------------
__device__ __forceinline__ void load_x_images(char* smem, const float* Xg0)
{
    const int tid = threadIdx.x;
    const float4* Xg = (const float4*)Xg0;
#pragma unroll
    for (int it = 0; it < 4; ++it) {
        int idx = tid + it * 256;            // 1024 chunks (row, ch)
        int row = idx >> 4;
        int ch = idx & 15;
        float4 f0 = Xg[row * 32 + ch * 2];
        float4 f1 = Xg[row * 32 + ch * 2 + 1];
        float f[8] = {f0.x, f0.y, f0.z, f0.w, f1.x, f1.y, f1.z, f1.w};
        uint4 hi, lo;
        cvt8(f, hi, lo);
        int off = row * 256 + ((ch ^ (row & 7)) << 4);
        *(uint4*)(smem + SOFF_XHI + off) = hi;
        *(uint4*)(smem + SOFF_XLO + off) = lo;
    }
}

// ---------------------------------------------------------------------------
// Projection mma (fused kernel): two-pass over W (hi then lo), 3-term split.
// ---------------------------------------------------------------------------
__device__ __forceinline__ void proj_mma(char* smem, u32 sb, const uint4* wsrc,
                                         float acc[2][4][4])
{
    const int tid = threadIdx.x;
    const int lane = tid & 31;
    const int w = tid >> 5;
    const int wr0 = (w & 1) * 32;
    const int wc0 = (w >> 1) * 32;
    const int quad = lane >> 3;
    const int l7 = lane & 7;
    const int arow0 = wr0 + l7 + (quad & 1) * 8;
    const int arow1 = arow0 + 16;
    const int axor0 = arow0 & 7;
    const int axor1 = arow1 & 7;
    const int ac_off = quad >> 1;
    const int krow_base = l7 + (quad & 1) * 8;
    const int bxor = krow_base & 7;

    __syncthreads();
#pragma unroll
    for (int it = 0; it < 8; ++it) {
        int i = tid + it * 256;
        *(uint4*)(smem + SOFF_W + i * 16) = wsrc[i];
    }
    __syncthreads();
#pragma unroll 1
    for (int ks = 0; ks < 8; ++ks) {
        u32 ah0[4], ah1[4], al0[4], al1[4];
        int offA0 = arow0 * 256 + (((ks * 2 + ac_off) ^ axor0) << 4);
        int offA1 = arow1 * 256 + (((ks * 2 + ac_off) ^ axor1) << 4);
        ldsm4(sb + SOFF_XHI + offA0, ah0[0], ah0[1], ah0[2], ah0[3]);
        ldsm4(sb + SOFF_XLO + offA0, al0[0], al0[1], al0[2], al0[3]);
        ldsm4(sb + SOFF_XHI + offA1, ah1[0], ah1[1], ah1[2], ah1[3]);
        ldsm4(sb + SOFF_XLO + offA1, al1[0], al1[1], al1[2], al1[3]);
#pragma unroll
        for (int p = 0; p < 2; ++p) {
            int chB = (wc0 >> 3) + p * 2 + (quad >> 1);
            int offB = (ks * 16 + krow_base) * 256 + ((chB ^ bxor) << 4);
            u32 wb0, wb1, wb2, wb3;
            ldsm4t(sb + SOFF_W + offB, wb0, wb1, wb2, wb3);
            mma_bf16(acc[0][2 * p],     ah0, wb0, wb1);
            mma_bf16(acc[0][2 * p + 1], ah0, wb2, wb3);
            mma_bf16(acc[1][2 * p],     ah1, wb0, wb1);
            mma_bf16(acc[1][2 * p + 1], ah1, wb2, wb3);
            mma_bf16(acc[0][2 * p],     al0, wb0, wb1);
            mma_bf16(acc[0][2 * p + 1], al0, wb2, wb3);
            mma_bf16(acc[1][2 * p],     al1, wb0, wb1);
            mma_bf16(acc[1][2 * p + 1], al1, wb2, wb3);
        }
    }
    __syncthreads();
#pragma unroll
    for (int it = 0; it < 8; ++it) {
        int i = tid + it * 256;
        *(uint4*)(smem + SOFF_W + i * 16) = wsrc[2048 + i];
    }
    __syncthreads();
#pragma unroll 1
    for (int ks = 0; ks < 8; ++ks) {
        u32 ah0[4], ah1[4];
        int offA0 = arow0 * 256 + (((ks * 2 + ac_off) ^ axor0) << 4);
        int offA1 = arow1 * 256 + (((ks * 2 + ac_off) ^ axor1) << 4);
        ldsm4(sb + SOFF_XHI + offA0, ah0[0], ah0[1], ah0[2], ah0[3]);
        ldsm4(sb + SOFF_XHI + offA1, ah1[0], ah1[1], ah1[2], ah1[3]);
#pragma unroll
        for (int p = 0; p < 2; ++p) {
            int chB = (wc0 >> 3) + p * 2 + (quad >> 1);
            int offB = (ks * 16 + krow_base) * 256 + ((chB ^ bxor) << 4);
            u32 wb0, wb1, wb2, wb3;
            ldsm4t(sb + SOFF_W + offB, wb0, wb1, wb2, wb3);
            mma_bf16(acc[0][2 * p],     ah0, wb0, wb1);
            mma_bf16(acc[0][2 * p + 1], ah0, wb2, wb3);
            mma_bf16(acc[1][2 * p],     ah1, wb0, wb1);
            mma_bf16(acc[1][2 * p + 1], ah1, wb2, wb3);
        }
    }
}

// ---------------------------------------------------------------------------
// Kernel 1: fused K/V projection + per-tile KtV/ksum partials (R10, unchanged).
// ---------------------------------------------------------------------------
__global__ __launch_bounds__(256, 2)
void fused_kv_ktv_kernel(const float* __restrict__ X,
                         const float* __restrict__ bk,
                         const float* __restrict__ bv)
{
    extern __shared__ char smem[];
    const u32 sb = (u32)__cvta_generic_to_shared(smem);
    float* ks2 = (float*)(smem + SOFF_KS2);          // [2][128]
    float* scr = (float*)(smem + SOFF_SCR);          // [4][1024] (post-KtV)

    const int tid = threadIdx.x;
    const int lane = tid & 31;
    const int w = tid >> 5;
    const long long tile = blockIdx.x;
    const long long m0 = tile * 64;

    load_x_images(smem, X + m0 * EE);

    const int wr0 = (w & 1) * 32;
    const int wc0 = (w >> 1) * 32;
    const int quad = lane >> 3;
    const int l7 = lane & 7;
    const int g = lane >> 2;
    const int t2 = lane & 3;

    float acc[2][4][4];

    // ================= Phase k =================
#pragma unroll
    for (int ii = 0; ii < 2; ++ii)
#pragma unroll
        for (int jj = 0; jj < 4; ++jj)
#pragma unroll
            for (int kk = 0; kk < 4; ++kk) acc[ii][jj][kk] = 0.f;
    proj_mma(smem, sb, g_wimg + 1 * 4096, acc);   // Wk

    {
        float ssum[4][2];
#pragma unroll
        for (int nt = 0; nt < 4; ++nt) { ssum[nt][0] = 0.f; ssum[nt][1] = 0.f; }
#pragma unroll
        for (int mt = 0; mt < 2; ++mt) {
            int r0 = wr0 + mt * 16 + g;
            int r1 = r0 + 8;
#pragma unroll
            for (int nt = 0; nt < 4; ++nt) {
                int col = wc0 + nt * 8 + t2 * 2;
                float2 bb = *(const float2*)(bk + col);
                float v0 = elu1(acc[mt][nt][0] + bb.x);
                float v1 = elu1(acc[mt][nt][1] + bb.y);
                float v2 = elu1(acc[mt][nt][2] + bb.x);
                float v3 = elu1(acc[mt][nt][3] + bb.y);
                ssum[nt][0] += v0 + v2;
                ssum[nt][1] += v1 + v3;
                int ch = col >> 3;
                int ib = (col & 7) * 2;
                u32 hi0, lo0, hi1, lo1;
                cvt2(v0, v1, hi0, lo0);
                cvt2(v2, v3, hi1, lo1);
                int off0 = r0 * 256 + ((ch ^ (r0 & 7)) << 4) + ib;
                int off1 = r1 * 256 + ((ch ^ (r1 & 7)) << 4) + ib;
                *(u32*)(smem + SOFF_KHI + off0) = hi0;
                *(u32*)(smem + SOFF_KLO + off0) = lo0;
                *(u32*)(smem + SOFF_KHI + off1) = hi1;
                *(u32*)(smem + SOFF_KLO + off1) = lo1;
            }
        }
#pragma unroll
        for (int nt = 0; nt < 4; ++nt) {
#pragma unroll
            for (int j = 0; j < 2; ++j) {
                float s = ssum[nt][j];
                s += __shfl_xor_sync(0xffffffffu, s, 4);
                s += __shfl_xor_sync(0xffffffffu, s, 8);
                s += __shfl_xor_sync(0xffffffffu, s, 16);
                ssum[nt][j] = s;
            }
        }
        if (lane < 4) {
#pragma unroll
            for (int nt = 0; nt < 4; ++nt) {
                ks2[(w & 1) * 128 + wc0 + nt * 8 + lane * 2]     = ssum[nt][0];
                ks2[(w & 1) * 128 + wc0 + nt * 8 + lane * 2 + 1] = ssum[nt][1];
            }
        }
    }

    // ================= Phase v =================
#pragma unroll
    for (int ii = 0; ii < 2; ++ii)
#pragma unroll
        for (int jj = 0; jj < 4; ++jj)
#pragma unroll
            for (int kk = 0; kk < 4; ++kk) acc[ii][jj][kk] = 0.f;
    proj_mma(smem, sb, g_wimg + 2 * 4096, acc);   // Wv

    __syncthreads();
    {
#pragma unroll
        for (int mt = 0; mt < 2; ++mt) {
            int r0 = wr0 + mt * 16 + g;
            int r1 = r0 + 8;
#pragma unroll
            for (int nt = 0; nt < 4; ++nt) {
                int col = wc0 + nt * 8 + t2 * 2;
                float2 bb = *(const float2*)(bv + col);
                float v0 = acc[mt][nt][0] + bb.x;
                float v1 = acc[mt][nt][1] + bb.y;
                float v2 = acc[mt][nt][2] + bb.x;
                float v3 = acc[mt][nt][3] + bb.y;
                int ch = col >> 3;
                int ib = (col & 7) * 2;
                u32 hi0, lo0, hi1, lo1;
                cvt2(v0, v1, hi0, lo0);
                cvt2(v2, v3, hi1, lo1);
                int off0 = r0 * 256 + ((ch ^ (r0 & 7)) << 4) + ib;
                int off1 = r1 * 256 + ((ch ^ (r1 & 7)) << 4) + ib;
                *(u32*)(smem + SOFF_VHI + off0) = hi0;
                *(u32*)(smem + SOFF_VLO + off0) = lo0;
                *(u32*)(smem + SOFF_VHI + off1) = hi1;
                *(u32*)(smem + SOFF_VLO + off1) = lo1;
            }
        }
    }
    __syncthreads();

    // ================= Phase KtV (tensor) =================
    {
        const int hh = w >> 1;
        const int cb = (w & 1) * 32;
#pragma unroll
        for (int ii = 0; ii < 2; ++ii)
#pragma unroll
            for (int jj = 0; jj < 4; ++jj)
#pragma unroll
                for (int kk = 0; kk < 4; ++kk) acc[ii][jj][kk] = 0.f;

#pragma unroll
        for (int ks = 0; ks < 2; ++ks) {
            u32 akh[2][4], akl[2][4];
            {
                int crowA = cb + ks * 16 + l7 + (quad >> 1) * 8;
                int ax = crowA & 7;
#pragma unroll
                for (int mt = 0; mt < 2; ++mt) {
                    int chA = hh * 4 + mt * 2 + (quad & 1);
                    int offA = crowA * 256 + ((chA ^ ax) << 4);
                    ldsm4t(sb + SOFF_KHI + offA, akh[mt][0], akh[mt][1], akh[mt][2], akh[mt][3]);
                    ldsm4t(sb + SOFF_KLO + offA, akl[mt][0], akl[mt][1], akl[mt][2], akl[mt][3]);
                }
            }
            int crowB = cb + ks * 16 + l7 + (quad & 1) * 8;
            int bx = crowB & 7;
#pragma unroll
            for (int p = 0; p < 2; ++p) {
                int chB = hh * 4 + p * 2 + (quad >> 1);
                int offB = crowB * 256 + ((chB ^ bx) << 4);
                u32 wb0, wb1, wb2, wb3;
                ldsm4t(sb + SOFF_VHI + offB, wb0, wb1, wb2, wb3);
                mma_bf16(acc[0][2 * p],     akh[0], wb0, wb1);
                mma_bf16(acc[0][2 * p + 1], akh[0], wb2, wb3);
                mma_bf16(acc[1][2 * p],     akh[1], wb0, wb1);
                mma_bf16(acc[1][2 * p + 1], akh[1], wb2, wb3);
                mma_bf16(acc[0][2 * p],     akl[0], wb0, wb1);
                mma_bf16(acc[0][2 * p + 1], akl[0], wb2, wb3);
                mma_bf16(acc[1][2 * p],     akl[1], wb0, wb1);
                mma_bf16(acc[1][2 * p + 1], akl[1], wb2, wb3);
                ldsm4t(sb + SOFF_VLO + offB, wb0, wb1, wb2, wb3);
                mma_bf16(acc[0][2 * p],     akh[0], wb0, wb1);
                mma_bf16(acc[0][2 * p + 1], akh[0], wb2, wb3);
                mma_bf16(acc[1][2 * p],     akh[1], wb0, wb1);
                mma_bf16(acc[1][2 * p + 1], akh[1], wb2, wb3);
            }
        }
        __syncthreads();

        if (w & 1) {
#pragma unroll
            for (int mt = 0; mt < 2; ++mt) {
#pragma unroll
                for (int nt = 0; nt < 4; ++nt) {
                    int i0 = (mt * 16 + g) * 32 + nt * 8 + t2 * 2;
                    int i1 = (mt * 16 + g + 8) * 32 + nt * 8 + t2 * 2;
                    *(float2*)(scr + hh * 1024 + i0) = make_float2(acc[mt][nt][0], acc[mt][nt][1]);
                    *(float2*)(scr + hh * 1024 + i1) = make_float2(acc[mt][nt][2], acc[mt][nt][3]);
                }
            }
        }
        __syncthreads();
        if (!(w & 1)) {
            float* dst = g_part + tile * 4096 + hh * 1024;
#pragma unroll
            for (int mt = 0; mt < 2; ++mt) {
#pragma unroll
                for (int nt = 0; nt < 4; ++nt) {
                    int i0 = (mt * 16 + g) * 32 + nt * 8 + t2 * 2;
                    int i1 = (mt * 16 + g + 8) * 32 + nt * 8 + t2 * 2;
                    float2 s0 = *(const float2*)(scr + hh * 1024 + i0);
                    float2 s1 = *(const float2*)(scr + hh * 1024 + i1);
                    *(float2*)(dst + i0) = make_float2(acc[mt][nt][0] + s0.x, acc[mt][nt][1] + s0.y);
                    *(float2*)(dst + i1) = make_float2(acc[mt][nt][2] + s1.x, acc[mt][nt][3] + s1.y);
                }
            }
        }
        if (tid < 128)
            g_ksum_part[tile * 128 + tid] = ks2[tid] + ks2[128 + tid];
    }
}

// ---------------------------------------------------------------------------
// Kernel 2: reduce 32 tile-partials per (br,h) -> bf16 images + final ksum.
// ---------------------------------------------------------------------------
__global__ __launch_bounds__(512)
void ktv_reduce_kernel()
{
    __shared__ float sred[512 * 9];
    __shared__ float skred[128];

    const int blk = blockIdx.x;           // br*H + h
    const int h = blk & 3;
    const int br = blk >> 2;
    const int t = threadIdx.x;
    const int chunk = t >> 2;
    const int seg = t & 3;
    const int d = chunk >> 2;
    const int cc = chunk & 3;

    float f[8];
#pragma unroll
    for (int i = 0; i < 8; ++i) f[i] = 0.f;
#pragma unroll
    for (int i = 0; i < 8; ++i) {
        int p = seg * 8 + i;
        const float4* pp = (const float4*)(g_part + ((long long)(br * 32 + p)) * 4096 +
                                           h * 1024 + d * 32 + cc * 8);
        float4 a = pp[0];
        float4 b = pp[1];
        f[0] += a.x; f[1] += a.y; f[2] += a.z; f[3] += a.w;
        f[4] += b.x; f[5] += b.y; f[6] += b.z; f[7] += b.w;
    }
#pragma unroll
    for (int j = 0; j < 8; ++j) sred[t * 9 + j] = f[j];

    if (t < 128) {
        int d2 = t & 31;
        int sg = t >> 5;
        float s = 0.f;
#pragma unroll
        for (int i = 0; i < 8; ++i)
            s += g_ksum_part[(br * 32 + sg * 8 + i) * 128 + h * 32 + d2];
        skred[t] = s;
    }
    __syncthreads();

    if (t < 128) {
        float fo[8];
#pragma unroll
        for (int j = 0; j < 8; ++j)
            fo[j] = (sred[(t * 4 + 0) * 9 + j] + sred[(t * 4 + 1) * 9 + j]) +
                    (sred[(t * 4 + 2) * 9 + j] + sred[(t * 4 + 3) * 9 + j]);
        uint4 hi, lo;
        cvt8(fo, hi, lo);
        int idx = h * 128 + t;
        g_ktvimg[(long long)br * 1024 + idx] = hi;
        g_ktvimg[(long long)br * 1024 + 512 + idx] = lo;
    } else if (t < 160) {
        int d2 = t - 128;
        g_ksum_final[blk * 32 + d2] =
            (skred[d2] + skred[32 + d2]) + (skred[64 + d2] + skred[96 + d2]);
    }
}

// ---------------------------------------------------------------------------
// Kernel 3: M=128 tout — q proj + t + out proj. 8 warps, warp grid 4x2,
// warp tile 32 rows x 64 cols. Single-pass (W hi+lo resident). 3 syncs.
// KtV in conflict-free 256B-stride region.
// ---------------------------------------------------------------------------
__global__ __launch_bounds__(256, 1)
void tout_kernel(const float* __restrict__ X, const float* __restrict__ bq,
                 const float* __restrict__ bo, float* __restrict__ out)
{
    extern __shared__ char smem[];
    const u32 sb = (u32)__cvta_generic_to_shared(smem);

    const int tid = threadIdx.x;
    const int lane = tid & 31;
    const int w = tid >> 5;
    const long long tile = blockIdx.x;
    const long long m0 = tile * 128;
    const int br = (int)(tile >> 4);

    const int wr0 = (w & 3) * 32;          // 4 warp-rows
    const int wc = w >> 2;                  // 2 warp-cols
    const int wc0 = wc * 64;
    const int quad = lane >> 3;
    const int l7 = lane & 7;
    const int arow0 = wr0 + l7 + (quad & 1) * 8;
    const int arow1 = arow0 + 16;
    const int axor0 = arow0 & 7;
    const int axor1 = arow1 & 7;
    const int ac_off = quad >> 1;
    const int krow_base = l7 + (quad & 1) * 8;
    const int bxor = krow_base & 7;
    const int g = lane >> 2;
    const int t2 = lane & 3;

    // ---- Phase 0: load KtV (256B-stride), X images (128 rows), Wq hi+lo ----
    {
        const uint4* src = g_ktvimg + (long long)br * 1024;
#pragma unroll
        for (int it = 0; it < 2; ++it) {
            int i = tid + it * 256;               // 512 chunks each image
            int h = i >> 7;
            int d = (i >> 2) & 31;
            int cc = i & 3;
            int off = (h * 32 + d) * 256 + (((h * 4 + cc) ^ (d & 7)) << 4);
            *(uint4*)(smem + T_KHI + off) = src[i];
            *(uint4*)(smem + T_KLO + off) = src[512 + i];
        }
    }
    {
        const float4* Xg = (const float4*)(X + m0 * EE);
#pragma unroll
        for (int it = 0; it < 8; ++it) {
            int idx = tid + it * 256;             // 2048 chunks (row, ch)
            int row = idx >> 4;
            int ch = idx & 15;
            float4 f0 = Xg[row * 32 + ch * 2];
            float4 f1 = Xg[row * 32 + ch * 2 + 1];
            float f[8] = {f0.x, f0.y, f0.z, f0.w, f1.x, f1.y, f1.z, f1.w};
            uint4 hi, lo;
            cvt8(f, hi, lo);
            int off = row * 256 + ((ch ^ (row & 7)) << 4);
            *(uint4*)(smem + T_AHI + off) = hi;
            *(uint4*)(smem + T_ALO + off) = lo;
        }
    }
    {
        const uint4* wsrc = g_wimg + 0 * 4096;    // Wq
#pragma unroll
        for (int it = 0; it < 8; ++it) {
            int i = tid + it * 256;
            *(uint4*)(smem + T_WHI + i * 16) = wsrc[i];
            *(uint4*)(smem + T_WLO + i * 16) = wsrc[2048 + i];
        }
    }
    __syncthreads();

    // ---- Phase 1: q = X @ Wq, single pass, warp tile 32x64 ----
    float acc[2][8][4];
#pragma unroll
    for (int ii = 0; ii < 2; ++ii)
#pragma unroll
        for (int jj = 0; jj < 8; ++jj)
#pragma unroll
            for (int kk = 0; kk < 4; ++kk) acc[ii][jj][kk] = 0.f;

#pragma unroll 1
    for (int ks = 0; ks < 8; ++ks) {
        u32 ah0[4], ah1[4], al0[4], al1[4];
        {
            int offA0 = arow0 * 256 + (((ks * 2 + ac_off) ^ axor0) << 4);
            int offA1 = arow1 * 256 + (((ks * 2 + ac_off) ^ axor1) << 4);
            ldsm4(sb + T_AHI + offA0, ah0[0], ah0[1], ah0[2], ah0[3]);
            ldsm4(sb + T_ALO + offA0, al0[0], al0[1], al0[2], al0[3]);
            ldsm4(sb + T_AHI + offA1, ah1[0], ah1[1], ah1[2], ah1[3]);
            ldsm4(sb + T_ALO + offA1, al1[0], al1[1], al1[2], al1[3]);
        }
#pragma unroll
        for (int p = 0; p < 4; ++p) {
            int chB = (wc0 >> 3) + p * 2 + (quad >> 1);
            int offB = (ks * 16 + krow_base) * 256 + ((chB ^ bxor) << 4);
            u32 wb0, wb1, wb2, wb3;
            ldsm4t(sb + T_WHI + offB, wb0, wb1, wb2, wb3);
            mma_bf16(acc[0][2 * p],     ah0, wb0, wb1);
            mma_bf16(acc[0][2 * p + 1], ah0, wb2, wb3);
            mma_bf16(acc[1][2 * p],     ah1, wb0, wb1);
            mma_bf16(acc[1][2 * p + 1], ah1, wb2, wb3);
            mma_bf16(acc[0][2 * p],     al0, wb0, wb1);
            mma_bf16(acc[0][2 * p + 1], al0, wb2, wb3);
            mma_bf16(acc[1][2 * p],     al1, wb0, wb1);
            mma_bf16(acc[1][2 * p + 1], al1, wb2, wb3);
            ldsm4t(sb + T_WLO + offB, wb0, wb1, wb2, wb3);
            mma_bf16(acc[0][2 * p],     ah0, wb0, wb1);
            mma_bf16(acc[0][2 * p + 1], ah0, wb2, wb3);
            mma_bf16(acc[1][2 * p],     ah1, wb0, wb1);
            mma_bf16(acc[1][2 * p + 1], ah1, wb2, wb3);
        }
    }
    __syncthreads();   // A (X) reads + W (Wq) reads done everywhere

    // ---- Phase 2: Wo copy into W region (overlaps epilogue + t-mma) ----
    {
        const uint4* wsrc = g_wimg + 3 * 4096;
#pragma unroll
        for (int it = 0; it < 8; ++it) {
            int i = tid + it * 256;
            *(uint4*)(smem + T_WHI + i * 16) = wsrc[i];
            *(uint4*)(smem + T_WLO + i * 16) = wsrc[2048 + i];
        }
    }

    // ---- q epilogue: bias + elu, Z dots per (row, head), q -> A image ----
    float zr[2][2][2];   // [mt][rowhalf][head01]
    {
        float ksm[8][2];
#pragma unroll
        for (int nt = 0; nt < 8; ++nt) {
            float2 kk = *(const float2*)(g_ksum_final + br * 128 + wc0 + nt * 8 + t2 * 2);
            ksm[nt][0] = kk.x;
            ksm[nt][1] = kk.y;
        }
#pragma unroll
        for (int mt = 0; mt < 2; ++mt) {
            int r0 = wr0 + mt * 16 + g;
            int r1 = r0 + 8;
            float dd[2][2] = {{0.f, 0.f}, {0.f, 0.f}};   // [rowhalf][head01]
#pragma unroll
            for (int nt = 0; nt < 8; ++nt) {
                int hsel = nt >> 2;
                int col = wc0 + nt * 8 + t2 * 2;
                float2 bb = *(const float2*)(bq + col);
                float v0 = elu1(acc[mt][nt][0] + bb.x);
                float v1 = elu1(acc[mt][nt][1] + bb.y);
                float v2 = elu1(acc[mt][nt][2] + bb.x);
                float v3 = elu1(acc[mt][nt][3] + bb.y);
                dd[0][hsel] = fmaf(v0, ksm[nt][0], fmaf(v1, ksm[nt][1], dd[0][hsel]));
                dd[1][hsel] = fmaf(v2, ksm[nt][0], fmaf(v3, ksm[nt][1], dd[1][hsel]));
                int ch = col >> 3;
                int ib = (col & 7) * 2;
                u32 hi0, lo0, hi1, lo1;
                cvt2(v0, v1, hi0, lo0);
                cvt2(v2, v3, hi1, lo1);
                int off0 = r0 * 256 + ((ch ^ (r0 & 7)) << 4) + ib;
                int off1 = r1 * 256 + ((ch ^ (r1 & 7)) << 4) + ib;
                *(u32*)(smem + T_AHI + off0) = hi0;
                *(u32*)(smem + T_ALO + off0) = lo0;
                *(u32*)(smem + T_AHI + off1) = hi1;
                *(u32*)(smem + T_ALO + off1) = lo1;
            }
#pragma unroll
            for (int rh = 0; rh < 2; ++rh)
#pragma unroll
                for (int hs = 0; hs < 2; ++hs) {
                    float s = dd[rh][hs];
                    s += __shfl_xor_sync(0xffffffffu, s, 1);
                    s += __shfl_xor_sync(0xffffffffu, s, 2);
                    zr[mt][rh][hs] = 1.0f / (s + 1e-6f);
                }
        }
    }

    // ---- Phase 3: t = q @ KtV (2 heads per warp, K=32 each), in-place ----
    {
#pragma unroll
        for (int ii = 0; ii < 2; ++ii)
#pragma unroll
            for (int jj = 0; jj < 8; ++jj)
#pragma unroll
                for (int kk = 0; kk < 4; ++kk) acc[ii][jj][kk] = 0.f;

#pragma unroll
        for (int ks = 0; ks < 2; ++ks) {
#pragma unroll
            for (int ph = 0; ph < 2; ++ph) {
                int h = wc * 2 + ph;
                u32 ah0[4], ah1[4], al0[4], al1[4];
                {
                    int chA = h * 4 + ks * 2 + ac_off;
                    int offA0 = arow0 * 256 + ((chA ^ axor0) << 4);
                    int offA1 = arow1 * 256 + ((chA ^ axor1) << 4);
                    ldsm4(sb + T_AHI + offA0, ah0[0], ah0[1], ah0[2], ah0[3]);
                    ldsm4(sb + T_ALO + offA0, al0[0], al0[1], al0[2], al0[3]);
                    ldsm4(sb + T_AHI + offA1, ah1[0], ah1[1], ah1[2], ah1[3]);
                    ldsm4(sb + T_ALO + offA1, al1[0], al1[1], al1[2], al1[3]);
                }
                int drow = ks * 16 + krow_base;       // row within head [0,32)
#pragma unroll
                for (int p = 0; p < 2; ++p) {
                    int chBl = h * 4 + p * 2 + (quad >> 1);
                    int offB = (h * 32 + drow) * 256 + ((chBl ^ (drow & 7)) << 4);
                    int ai = ph * 4 + p * 2;
                    u32 wb0, wb1, wb2, wb3;
                    ldsm4t(sb + T_KHI + offB, wb0, wb1, wb2, wb3);
                    mma_bf16(acc[0][ai],     ah0, wb0, wb1);
                    mma_bf16(acc[0][ai + 1], ah0, wb2, wb3);
                    mma_bf16(acc[1][ai],     ah1, wb0, wb1);
                    mma_bf16(acc[1][ai + 1], ah1, wb2, wb3);
                    mma_bf16(acc[0][ai],     al0, wb0, wb1);
                    mma_bf16(acc[0][ai + 1], al0, wb2, wb3);
                    mma_bf16(acc[1][ai],     al1, wb0, wb1);
                    mma_bf16(acc[1][ai + 1], al1, wb2, wb3);
                    ldsm4t(sb + T_KLO + offB, wb0, wb1, wb2, wb3);
                    mma_bf16(acc[0][ai],     ah0, wb0, wb1);
                    mma_bf16(acc[0][ai + 1], ah0, wb2, wb3);
                    mma_bf16(acc[1][ai],     ah1, wb0, wb1);
                    mma_bf16(acc[1][ai + 1], ah1, wb2, wb3);
                }
            }
        }

        // Z-scale + write t back into the A image (warp-local chunks; no sync)
#pragma unroll
        for (int mt = 0; mt < 2; ++mt) {
            int r0 = wr0 + mt * 16 + g;
            int r1 = r0 + 8;
#pragma unroll
            for (int nt = 0; nt < 8; ++nt) {
                int hsel = nt >> 2;
                float z0 = zr[mt][0][hsel];
                float z1 = zr[mt][1][hsel];
                int col = wc0 + nt * 8 + t2 * 2;
                int ch = col >> 3;
                int ib = (col & 7) * 2;
                u32 hi0, lo0, hi1, lo1;
                cvt2(acc[mt][nt][0] * z0, acc[mt][nt][1] * z0, hi0, lo0);
                cvt2(acc[mt][nt][2] * z1, acc[mt][nt][3] * z1, hi1, lo1);
                int off0 = r0 * 256 + ((ch ^ (r0 & 7)) << 4) + ib;
                int off1 = r1 * 256 + ((ch ^ (r1 & 7)) << 4) + ib;
                *(u32*)(smem + T_AHI + off0) = hi0;
                *(u32*)(smem + T_ALO + off0) = lo0;
                *(u32*)(smem + T_AHI + off1) = hi1;
                *(u32*)(smem + T_ALO + off1) = lo1;
            }
        }
    }
    __syncthreads();   // t images + Wo images visible everywhere

    // ---- Phase 4: out = t @ Wo + bo (K=128, single pass) ----
#pragma unroll
    for (int ii = 0; ii < 2; ++ii)
#pragma unroll
        for (int jj = 0; jj < 8; ++jj)
#pragma unroll
            for (int kk = 0; kk < 4; ++kk) acc[ii][jj][kk] = 0.f;

#pragma unroll 1
    for (int ks = 0; ks < 8; ++ks) {
        u32 ah0[4], ah1[4], al0[4], al1[4];
        {
            int offA0 = arow0 * 256 + (((ks * 2 + ac_off) ^ axor0) << 4);
            int offA1 = arow1 * 256 + (((ks * 2 + ac_off) ^ axor1) << 4);
            ldsm4(sb + T_AHI + offA0, ah0[0], ah0[1], ah0[2], ah0[3]);
            ldsm4(sb + T_ALO + offA0, al0[0], al0[1], al0[2], al0[3]);
            ldsm4(sb + T_AHI + offA1, ah1[0], ah1[1], ah1[2], ah1[3]);
            ldsm4(sb + T_ALO + offA1, al1[0], al1[1], al1[2], al1[3]);
        }
#pragma unroll
        for (int p = 0; p < 4; ++p) {
            int chB = (wc0 >> 3) + p * 2 + (quad >> 1);
            int offB = (ks * 16 + krow_base) * 256 + ((chB ^ bxor) << 4);
            u32 wb0, wb1, wb2, wb3;
            ldsm4t(sb + T_WHI + offB, wb0, wb1, wb2, wb3);
            mma_bf16(acc[0][2 * p],     ah0, wb0, wb1);
            mma_bf16(acc[0][2 * p + 1], ah0, wb2, wb3);
            mma_bf16(acc[1][2 * p],     ah1, wb0, wb1);
            mma_bf16(acc[1][2 * p + 1], ah1, wb2, wb3);
            mma_bf16(acc[0][2 * p],     al0, wb0, wb1);
            mma_bf16(acc[0][2 * p + 1], al0, wb2, wb3);
            mma_bf16(acc[1][2 * p],     al1, wb0, wb1);
            mma_bf16(acc[1][2 * p + 1], al1, wb2, wb3);
            ldsm4t(sb + T_WLO + offB, wb0, wb1, wb2, wb3);
            mma_bf16(acc[0][2 * p],     ah0, wb0, wb1);
            mma_bf16(acc[0][2 * p + 1], ah0, wb2, wb3);
            mma_bf16(acc[1][2 * p],     ah1, wb0, wb1);
            mma_bf16(acc[1][2 * p + 1], ah1, wb2, wb3);
        }
    }

#pragma unroll
    for (int mt = 0; mt < 2; ++mt) {
#pragma unroll
        for (int nt = 0; nt < 8; ++nt) {
            int col = wc0 + nt * 8 + t2 * 2;
            float2 bb = *(const float2*)(bo + col);
            long long r0g = m0 + wr0 + mt * 16 + g;
            float v0 = acc[mt][nt][0] + bb.x;
            float v1 = acc[mt][nt][1] + bb.y;
            float v2 = acc[mt][nt][2] + bb.x;
            float v3 = acc[mt][nt][3] + bb.y;
            *(float2*)(out + r0g * EE + col)       = make_float2(v0, v1);
            *(float2*)(out + (r0g + 8) * EE + col) = make_float2(v2, v3);
        }
    }
}

// ---------------------------------------------------------------------------
extern "C" void kernel_launch(void* const* d_in, const int* in_sizes, int n_in,
                              void* d_out, int out_size)
{
    const float* X  = (const float*)d_in[0];
    const float* Wq = (const float*)d_in[1];
    const float* bq = (const float*)d_in[2];
    const float* Wk = (const float*)d_in[3];
    const float* bk = (const float*)d_in[4];
    const float* Wv = (const float*)d_in[5];
    const float* bv = (const float*)d_in[6];
    const float* Wo = (const float*)d_in[7];
    const float* bo = (const float*)d_in[8];
    float* out = (float*)d_out;

    cudaFuncSetAttribute(fused_kv_ktv_kernel, cudaFuncAttributeMaxDynamicSharedMemorySize, SMEM_FUSED);
    cudaFuncSetAttribute(tout_kernel, cudaFuncAttributeMaxDynamicSharedMemorySize, SMEM_TOUT);

    prep_w_kernel<<<4, 256>>>(Wq, Wk, Wv, Wo);
    fused_kv_ktv_kernel<<<NTILES, 256, SMEM_FUSED>>>(X, bk, bv);
    ktv_reduce_kernel<<<NKV, 512>>>();
    tout_kernel<<<NTILES / 2, 256, SMEM_TOUT>>>(X, bq, bo, out);
}

// round 13
// speedup vs baseline: 1.1073x; 1.1073x over previous
#include <cuda_runtime.h>
#include <cuda_bf16.h>
#include <math.h>

typedef unsigned int u32;

// Problem constants
constexpr int BB = 2, RR = 64, CC = 2048, EE = 128, HH = 4, DH = 32;
constexpr long long MROWS = (long long)BB * RR * CC;        // 262144
constexpr int NTILES = (int)(MROWS / 64);                    // 4096
constexpr int NKV = BB * RR * HH;                            // 512
constexpr int NBR = BB * RR;                                 // 128

// Scratch (device globals — no runtime allocation)
__device__ float g_part[(long long)NTILES * HH * DH * DH];   // 67 MB KtV partials
__device__ float g_ksum_part[NTILES * EE];                   // 2 MB
__device__ float g_ksum_final[NKV * DH];                     // 64 KB
// Pre-swizzled bf16 weight images: [matrix 0..3][hi 2048 | lo 2048] uint4 chunks
__device__ uint4 g_wimg[4 * 4096];
// Pre-swizzled bf16 KtV images: per br: [hi 512 | lo 512] uint4 (h,d,cc)
__device__ uint4 g_ktvimg[NBR * 1024];

// ---------------------------------------------------------------------------
// helpers
// ---------------------------------------------------------------------------
__device__ __forceinline__ void ldsm4(u32 a, u32& r0, u32& r1, u32& r2, u32& r3) {
    asm volatile("ldmatrix.sync.aligned.m8n8.x4.shared.b16 {%0,%1,%2,%3},[%4];"
                 : "=r"(r0), "=r"(r1), "=r"(r2), "=r"(r3) : "r"(a));
}
__device__ __forceinline__ void ldsm4t(u32 a, u32& r0, u32& r1, u32& r2, u32& r3) {
    asm volatile("ldmatrix.sync.aligned.m8n8.x4.trans.shared.b16 {%0,%1,%2,%3},[%4];"
                 : "=r"(r0), "=r"(r1), "=r"(r2), "=r"(r3) : "r"(a));
}
__device__ __forceinline__ void mma_bf16(float c[4], const u32 a[4], u32 b0, u32 b1) {
    asm volatile(
        "mma.sync.aligned.m16n8k16.row.col.f32.bf16.bf16.f32 "
        "{%0,%1,%2,%3},{%4,%5,%6,%7},{%8,%9},{%0,%1,%2,%3};"
        : "+f"(c[0]), "+f"(c[1]), "+f"(c[2]), "+f"(c[3])
        : "r"(a[0]), "r"(a[1]), "r"(a[2]), "r"(a[3]), "r"(b0), "r"(b1));
}

__device__ __forceinline__ void cvt2(float a, float b, u32& hi, u32& lo) {
    __nv_bfloat16 ah16 = __float2bfloat16_rn(a);
    __nv_bfloat16 bh16 = __float2bfloat16_rn(b);
    float ar = a - __bfloat162float(ah16);
    float br = b - __bfloat162float(bh16);
    __nv_bfloat162 hp = __halves2bfloat162(ah16, bh16);
    __nv_bfloat162 lp = __floats2bfloat162_rn(ar, br);
    hi = *(u32*)&hp;
    lo = *(u32*)&lp;
}

__device__ __forceinline__ void cvt8(const float* f, uint4& hi, uint4& lo) {
    u32 h[4];
    u32 l[4];
#pragma unroll
    for (int i = 0; i < 4; ++i) cvt2(f[2 * i], f[2 * i + 1], h[i], l[i]);
    hi = make_uint4(h[0], h[1], h[2], h[3]);
    lo = make_uint4(l[0], l[1], l[2], l[3]);
}

__device__ __forceinline__ float elu1(float x) {
    return (x > 0.f) ? (x + 1.f) : expf(x);
}

// ---- smem layout (bytes), fused kv/KtV kernel ----
constexpr int SOFF_XHI = 0;
constexpr int SOFF_XLO = 16384;
constexpr int SOFF_W   = 32768;
constexpr int SOFF_VHI = 32768;
constexpr int SOFF_VLO = 49152;
constexpr int SOFF_KHI = 65536;
constexpr int SOFF_KLO = 81920;
constexpr int SOFF_SCR = 65536;
constexpr int SOFF_KS2 = 98304;
constexpr int SMEM_FUSED = 98304 + 1024;   // 99328

// ---- tout smem layout: A [0,32K), W [32K,96K), KtV compact [96K,112K) ----
constexpr int SOFF_AHI = 0;
constexpr int SOFF_ALO = 16384;
constexpr int SOFF_WHI2 = 32768;
constexpr int SOFF_WLO2 = 65536;
constexpr int SOFF_KTVHI = 98304;           // reserved (unused in this rev)
constexpr int SOFF_KTVLO = 98304 + 8192;
constexpr int SMEM_TOUT = 114688;           // 112 KB (2 CTAs/SM)

// ---------------------------------------------------------------------------
// Kernel 0: precompute bf16 hi/lo swizzled images of the 4 weight matrices.
// ---------------------------------------------------------------------------
__global__ __launch_bounds__(256)
void prep_w_kernel(const float* __restrict__ Wq, const float* __restrict__ Wk,
                   const float* __restrict__ Wv, const float* __restrict__ Wo)
{
    const float* Ws[4] = {Wq, Wk, Wv, Wo};
    const float4* W = (const float4*)Ws[blockIdx.x];
    uint4* dst = g_wimg + blockIdx.x * 4096;
    const int tid = threadIdx.x;
#pragma unroll
    for (int it = 0; it < 8; ++it) {
        int idx = tid + it * 256;            // 2048 chunks
        int row = idx >> 4;
        int ch = idx & 15;
        float4 f0 = W[row * 32 + ch * 2];
        float4 f1 = W[row * 32 + ch * 2 + 1];
        float f[8] = {f0.x, f0.y, f0.z, f0.w, f1.x, f1.y, f1.z, f1.w};
        uint4 hi, lo;
        cvt8(f, hi, lo);
        int c = row * 16 + (ch ^ (row & 7));
        dst[c] = hi;
        dst[2048 + c] = lo;
    }
}

// ---------------------------------------------------------------------------
// X tile load helper: 64x128 f32 -> bf16 hi/lo swizzled images at XHI/XLO.
// ---------------------------------------------------------------------------
__device__ __forceinline__ void load_x_images(char* smem, const float* Xg0)
{
    const int tid = threadIdx.x;
    const float4* Xg = (const float4*)Xg0;
#pragma unroll
    for (int it = 0; it < 4; ++it) {
        int idx = tid + it * 256;            // 1024 chunks (row, ch)
        int row = idx >> 4;
        int ch = idx & 15;
        float4 f0 = Xg[row * 32 + ch * 2];
        float4 f1 = Xg[row * 32 + ch * 2 + 1];
        float f[8] = {f0.x, f0.y, f0.z, f0.w, f1.x, f1.y, f1.z, f1.w};
        uint4 hi, lo;
        cvt8(f, hi, lo);
        int off = row * 256 + ((ch ^ (row & 7)) << 4);
        *(uint4*)(smem + SOFF_XHI + off) = hi;
        *(uint4*)(smem + SOFF_XLO + off) = lo;
    }
}

// ---------------------------------------------------------------------------
// Projection mma: two-pass over W (hi then lo), accumulating 3-term split.
// K-loops use unroll 2 for cross-iteration ldsm/mma overlap.
// ---------------------------------------------------------------------------
__device__ __forceinline__ void proj_mma(char* smem, u32 sb, const uint4* wsrc,
                                         float acc[2][4][4])
{
    const int tid = threadIdx.x;
    const int lane = tid & 31;
    const int w = tid >> 5;
    const int wr0 = (w & 1) * 32;
    const int wc0 = (w >> 1) * 32;
    const int quad = lane >> 3;
    const int l7 = lane & 7;
    const int arow0 = wr0 + l7 + (quad & 1) * 8;
    const int arow1 = arow0 + 16;
    const int axor0 = arow0 & 7;
    const int axor1 = arow1 & 7;
    const int ac_off = quad >> 1;
    const int krow_base = l7 + (quad & 1) * 8;
    const int bxor = krow_base & 7;

    // ---- pass 1: W hi (terms Xhi*Whi + Xlo*Whi) ----
    __syncthreads();
#pragma unroll
    for (int it = 0; it < 8; ++it) {
        int i = tid + it * 256;
        *(uint4*)(smem + SOFF_W + i * 16) = wsrc[i];
    }
    __syncthreads();
#pragma unroll 2
    for (int ks = 0; ks < 8; ++ks) {
        u32 ah0[4], ah1[4], al0[4], al1[4];
        int offA0 = arow0 * 256 + (((ks * 2 + ac_off) ^ axor0) << 4);
        int offA1 = arow1 * 256 + (((ks * 2 + ac_off) ^ axor1) << 4);
        ldsm4(sb + SOFF_XHI + offA0, ah0[0], ah0[1], ah0[2], ah0[3]);
        ldsm4(sb + SOFF_XLO + offA0, al0[0], al0[1], al0[2], al0[3]);
        ldsm4(sb + SOFF_XHI + offA1, ah1[0], ah1[1], ah1[2], ah1[3]);
        ldsm4(sb + SOFF_XLO + offA1, al1[0], al1[1], al1[2], al1[3]);
#pragma unroll
        for (int p = 0; p < 2; ++p) {
            int chB = (wc0 >> 3) + p * 2 + (quad >> 1);
            int offB = (ks * 16 + krow_base) * 256 + ((chB ^ bxor) << 4);
            u32 wb0, wb1, wb2, wb3;
            ldsm4t(sb + SOFF_W + offB, wb0, wb1, wb2, wb3);
            mma_bf16(acc[0][2 * p],     ah0, wb0, wb1);
            mma_bf16(acc[0][2 * p + 1], ah0, wb2, wb3);
            mma_bf16(acc[1][2 * p],     ah1, wb0, wb1);
            mma_bf16(acc[1][2 * p + 1], ah1, wb2, wb3);
            mma_bf16(acc[0][2 * p],     al0, wb0, wb1);
            mma_bf16(acc[0][2 * p + 1], al0, wb2, wb3);
            mma_bf16(acc[1][2 * p],     al1, wb0, wb1);
            mma_bf16(acc[1][2 * p + 1], al1, wb2, wb3);
        }
    }
    // ---- pass 2: W lo (term Xhi*Wlo) ----
    __syncthreads();
#pragma unroll
    for (int it = 0; it < 8; ++it) {
        int i = tid + it * 256;
        *(uint4*)(smem + SOFF_W + i * 16) = wsrc[2048 + i];
    }
    __syncthreads();
#pragma unroll 2
    for (int ks = 0; ks < 8; ++ks) {
        u32 ah0[4], ah1[4];
        int offA0 = arow0 * 256 + (((ks * 2 + ac_off) ^ axor0) << 4);
        int offA1 = arow1 * 256 + (((ks * 2 + ac_off) ^ axor1) << 4);
        ldsm4(sb + SOFF_XHI + offA0, ah0[0], ah0[1], ah0[2], ah0[3]);
        ldsm4(sb + SOFF_XHI + offA1, ah1[0], ah1[1], ah1[2], ah1[3]);
#pragma unroll
        for (int p = 0; p < 2; ++p) {
            int chB = (wc0 >> 3) + p * 2 + (quad >> 1);
            int offB = (ks * 16 + krow_base) * 256 + ((chB ^ bxor) << 4);
            u32 wb0, wb1, wb2, wb3;
            ldsm4t(sb + SOFF_W + offB, wb0, wb1, wb2, wb3);
            mma_bf16(acc[0][2 * p],     ah0, wb0, wb1);
            mma_bf16(acc[0][2 * p + 1], ah0, wb2, wb3);
            mma_bf16(acc[1][2 * p],     ah1, wb0, wb1);
            mma_bf16(acc[1][2 * p + 1], ah1, wb2, wb3);
        }
    }
}

// ---------------------------------------------------------------------------
// Kernel 1: fused K/V projection + per-tile KtV/ksum partials.
// ---------------------------------------------------------------------------
__global__ __launch_bounds__(256, 2)
void fused_kv_ktv_kernel(const float* __restrict__ X,
                         const float* __restrict__ bk,
                         const float* __restrict__ bv)
{
    extern __shared__ char smem[];
    const u32 sb = (u32)__cvta_generic_to_shared(smem);
    float* ks2 = (float*)(smem + SOFF_KS2);          // [2][128]
    float* scr = (float*)(smem + SOFF_SCR);          // [4][1024] (post-KtV)

    const int tid = threadIdx.x;
    const int lane = tid & 31;
    const int w = tid >> 5;
    const long long tile = blockIdx.x;
    const long long m0 = tile * 64;

    load_x_images(smem, X + m0 * EE);

    const int wr0 = (w & 1) * 32;
    const int wc0 = (w >> 1) * 32;
    const int quad = lane >> 3;
    const int l7 = lane & 7;
    const int g = lane >> 2;
    const int t2 = lane & 3;

    float acc[2][4][4];

    // ================= Phase k =================
#pragma unroll
    for (int ii = 0; ii < 2; ++ii)
#pragma unroll
        for (int jj = 0; jj < 4; ++jj)
#pragma unroll
            for (int kk = 0; kk < 4; ++kk) acc[ii][jj][kk] = 0.f;
    proj_mma(smem, sb, g_wimg + 1 * 4096, acc);   // Wk

    // epilogue: bias + elu -> k image (smem) + ksum partial (shfl)
    {
        float ssum[4][2];
#pragma unroll
        for (int nt = 0; nt < 4; ++nt) { ssum[nt][0] = 0.f; ssum[nt][1] = 0.f; }
#pragma unroll
        for (int mt = 0; mt < 2; ++mt) {
            int r0 = wr0 + mt * 16 + g;
            int r1 = r0 + 8;
#pragma unroll
            for (int nt = 0; nt < 4; ++nt) {
                int col = wc0 + nt * 8 + t2 * 2;
                float2 bb = *(const float2*)(bk + col);
                float v0 = elu1(acc[mt][nt][0] + bb.x);
                float v1 = elu1(acc[mt][nt][1] + bb.y);
                float v2 = elu1(acc[mt][nt][2] + bb.x);
                float v3 = elu1(acc[mt][nt][3] + bb.y);
                ssum[nt][0] += v0 + v2;
                ssum[nt][1] += v1 + v3;
                int ch = col >> 3;
                int ib = (col & 7) * 2;
                u32 hi0, lo0, hi1, lo1;
                cvt2(v0, v1, hi0, lo0);
                cvt2(v2, v3, hi1, lo1);
                int off0 = r0 * 256 + ((ch ^ (r0 & 7)) << 4) + ib;
                int off1 = r1 * 256 + ((ch ^ (r1 & 7)) << 4) + ib;
                *(u32*)(smem + SOFF_KHI + off0) = hi0;
                *(u32*)(smem + SOFF_KLO + off0) = lo0;
                *(u32*)(smem + SOFF_KHI + off1) = hi1;
                *(u32*)(smem + SOFF_KLO + off1) = lo1;
            }
        }
#pragma unroll
        for (int nt = 0; nt < 4; ++nt) {
#pragma unroll
            for (int j = 0; j < 2; ++j) {
                float s = ssum[nt][j];
                s += __shfl_xor_sync(0xffffffffu, s, 4);
                s += __shfl_xor_sync(0xffffffffu, s, 8);
                s += __shfl_xor_sync(0xffffffffu, s, 16);
                ssum[nt][j] = s;
            }
        }
        if (lane < 4) {
#pragma unroll
            for (int nt = 0; nt < 4; ++nt) {
                ks2[(w & 1) * 128 + wc0 + nt * 8 + lane * 2]     = ssum[nt][0];
                ks2[(w & 1) * 128 + wc0 + nt * 8 + lane * 2 + 1] = ssum[nt][1];
            }
        }
    }

    // ================= Phase v =================
#pragma unroll
    for (int ii = 0; ii < 2; ++ii)
#pragma unroll
        for (int jj = 0; jj < 4; ++jj)
#pragma unroll
            for (int kk = 0; kk < 4; ++kk) acc[ii][jj][kk] = 0.f;
    proj_mma(smem, sb, g_wimg + 2 * 4096, acc);   // Wv

    __syncthreads();   // Wv_lo reads done before overwriting W slot with v image
    {
#pragma unroll
        for (int mt = 0; mt < 2; ++mt) {
            int r0 = wr0 + mt * 16 + g;
            int r1 = r0 + 8;
#pragma unroll
            for (int nt = 0; nt < 4; ++nt) {
                int col = wc0 + nt * 8 + t2 * 2;
                float2 bb = *(const float2*)(bv + col);
                float v0 = acc[mt][nt][0] + bb.x;
                float v1 = acc[mt][nt][1] + bb.y;
                float v2 = acc[mt][nt][2] + bb.x;
                float v3 = acc[mt][nt][3] + bb.y;
                int ch = col >> 3;
                int ib = (col & 7) * 2;
                u32 hi0, lo0, hi1, lo1;
                cvt2(v0, v1, hi0, lo0);
                cvt2(v2, v3, hi1, lo1);
                int off0 = r0 * 256 + ((ch ^ (r0 & 7)) << 4) + ib;
                int off1 = r1 * 256 + ((ch ^ (r1 & 7)) << 4) + ib;
                *(u32*)(smem + SOFF_VHI + off0) = hi0;
                *(u32*)(smem + SOFF_VLO + off0) = lo0;
                *(u32*)(smem + SOFF_VHI + off1) = hi1;
                *(u32*)(smem + SOFF_VLO + off1) = lo1;
            }
        }
    }
    __syncthreads();   // k/v images visible to all

    // ================= Phase KtV (tensor) =================
    {
        const int hh = w >> 1;
        const int cb = (w & 1) * 32;
#pragma unroll
        for (int ii = 0; ii < 2; ++ii)
#pragma unroll
            for (int jj = 0; jj < 4; ++jj)
#pragma unroll
                for (int kk = 0; kk < 4; ++kk) acc[ii][jj][kk] = 0.f;

#pragma unroll
        for (int ks = 0; ks < 2; ++ks) {
            u32 akh[2][4], akl[2][4];
            {
                int crowA = cb + ks * 16 + l7 + (quad >> 1) * 8;
                int ax = crowA & 7;
#pragma unroll
                for (int mt = 0; mt < 2; ++mt) {
                    int chA = hh * 4 + mt * 2 + (quad & 1);
                    int offA = crowA * 256 + ((chA ^ ax) << 4);
                    ldsm4t(sb + SOFF_KHI + offA, akh[mt][0], akh[mt][1], akh[mt][2], akh[mt][3]);
                    ldsm4t(sb + SOFF_KLO + offA, akl[mt][0], akl[mt][1], akl[mt][2], akl[mt][3]);
                }
            }
            int crowB = cb + ks * 16 + l7 + (quad & 1) * 8;
            int bx = crowB & 7;
#pragma unroll
            for (int p = 0; p < 2; ++p) {
                int chB = hh * 4 + p * 2 + (quad >> 1);
                int offB = crowB * 256 + ((chB ^ bx) << 4);
                u32 wb0, wb1, wb2, wb3;
                ldsm4t(sb + SOFF_VHI + offB, wb0, wb1, wb2, wb3);
                mma_bf16(acc[0][2 * p],     akh[0], wb0, wb1);
                mma_bf16(acc[0][2 * p + 1], akh[0], wb2, wb3);
                mma_bf16(acc[1][2 * p],     akh[1], wb0, wb1);
                mma_bf16(acc[1][2 * p + 1], akh[1], wb2, wb3);
                mma_bf16(acc[0][2 * p],     akl[0], wb0, wb1);
                mma_bf16(acc[0][2 * p + 1], akl[0], wb2, wb3);
                mma_bf16(acc[1][2 * p],     akl[1], wb0, wb1);
                mma_bf16(acc[1][2 * p + 1], akl[1], wb2, wb3);
                ldsm4t(sb + SOFF_VLO + offB, wb0, wb1, wb2, wb3);
                mma_bf16(acc[0][2 * p],     akh[0], wb0, wb1);
                mma_bf16(acc[0][2 * p + 1], akh[0], wb2, wb3);
                mma_bf16(acc[1][2 * p],     akh[1], wb0, wb1);
                mma_bf16(acc[1][2 * p + 1], akh[1], wb2, wb3);
            }
        }
        __syncthreads();   // k image reads done; scratch region free

        if (w & 1) {
#pragma unroll
            for (int mt = 0; mt < 2; ++mt) {
#pragma unroll
                for (int nt = 0; nt < 4; ++nt) {
                    int i0 = (mt * 16 + g) * 32 + nt * 8 + t2 * 2;
                    int i1 = (mt * 16 + g + 8) * 32 + nt * 8 + t2 * 2;
                    *(float2*)(scr + hh * 1024 + i0) = make_float2(acc[mt][nt][0], acc[mt][nt][1]);
                    *(float2*)(scr + hh * 1024 + i1) = make_float2(acc[mt][nt][2], acc[mt][nt][3]);
                }
            }
        }
        __syncthreads();
        if (!(w & 1)) {
            float* dst = g_part + tile * 4096 + hh * 1024;
#pragma unroll
            for (int mt = 0; mt < 2; ++mt) {
#pragma unroll
                for (int nt = 0; nt < 4; ++nt) {
                    int i0 = (mt * 16 + g) * 32 + nt * 8 + t2 * 2;
                    int i1 = (mt * 16 + g + 8) * 32 + nt * 8 + t2 * 2;
                    float2 s0 = *(const float2*)(scr + hh * 1024 + i0);
                    float2 s1 = *(const float2*)(scr + hh * 1024 + i1);
                    *(float2*)(dst + i0) = make_float2(acc[mt][nt][0] + s0.x, acc[mt][nt][1] + s0.y);
                    *(float2*)(dst + i1) = make_float2(acc[mt][nt][2] + s1.x, acc[mt][nt][3] + s1.y);
                }
            }
        }
        if (tid < 128)
            g_ksum_part[tile * 128 + tid] = ks2[tid] + ks2[128 + tid];
    }
}

// ---------------------------------------------------------------------------
// Kernel 2: reduce 32 tile-partials per (br,h) -> bf16 images + final ksum.
// ---------------------------------------------------------------------------
__global__ __launch_bounds__(512)
void ktv_reduce_kernel()
{
    __shared__ float sred[512 * 9];
    __shared__ float skred[128];

    const int blk = blockIdx.x;           // br*H + h
    const int h = blk & 3;
    const int br = blk >> 2;
    const int t = threadIdx.x;
    const int chunk = t >> 2;
    const int seg = t & 3;
    const int d = chunk >> 2;
    const int cc = chunk & 3;

    float f[8];
#pragma unroll
    for (int i = 0; i < 8; ++i) f[i] = 0.f;
#pragma unroll
    for (int i = 0; i < 8; ++i) {
        int p = seg * 8 + i;
        const float4* pp = (const float4*)(g_part + ((long long)(br * 32 + p)) * 4096 +
                                           h * 1024 + d * 32 + cc * 8);
        float4 a = pp[0];
        float4 b = pp[1];
        f[0] += a.x; f[1] += a.y; f[2] += a.z; f[3] += a.w;
        f[4] += b.x; f[5] += b.y; f[6] += b.z; f[7] += b.w;
    }
#pragma unroll
    for (int j = 0; j < 8; ++j) sred[t * 9 + j] = f[j];

    if (t < 128) {
        int d2 = t & 31;
        int sg = t >> 5;
        float s = 0.f;
#pragma unroll
        for (int i = 0; i < 8; ++i)
            s += g_ksum_part[(br * 32 + sg * 8 + i) * 128 + h * 32 + d2];
        skred[t] = s;
    }
    __syncthreads();

    if (t < 128) {
        float fo[8];
#pragma unroll
        for (int j = 0; j < 8; ++j)
            fo[j] = (sred[(t * 4 + 0) * 9 + j] + sred[(t * 4 + 1) * 9 + j]) +
                    (sred[(t * 4 + 2) * 9 + j] + sred[(t * 4 + 3) * 9 + j]);
        uint4 hi, lo;
        cvt8(fo, hi, lo);
        int idx = h * 128 + t;
        g_ktvimg[(long long)br * 1024 + idx] = hi;
        g_ktvimg[(long long)br * 1024 + 512 + idx] = lo;
    } else if (t < 160) {
        int d2 = t - 128;
        g_ksum_final[blk * 32 + d2] =
            (skred[d2] + skred[32 + d2]) + (skred[64 + d2] + skred[96 + d2]);
    }
}

// ---------------------------------------------------------------------------
// Kernel 3: q projection + t + output projection (R10 structure; K-loops
// unrolled x2 for ldsm/mma overlap).
// ---------------------------------------------------------------------------
__global__ __launch_bounds__(256, 2)
void tout_kernel(const float* __restrict__ X, const float* __restrict__ bq,
                 const float* __restrict__ bo, float* __restrict__ out)
{
    extern __shared__ char smem[];
    const u32 sb = (u32)__cvta_generic_to_shared(smem);

    const int tid = threadIdx.x;
    const int lane = tid & 31;
    const int w = tid >> 5;
    const long long tile = blockIdx.x;
    const long long m0 = tile * 64;
    const int br = (int)(tile >> 5);

    const int wr0 = (w & 1) * 32;
    const int wc0 = (w >> 1) * 32;
    const int hh = w >> 1;
    const int quad = lane >> 3;
    const int l7 = lane & 7;
    const int arow0 = wr0 + l7 + (quad & 1) * 8;
    const int arow1 = arow0 + 16;
    const int axor0 = arow0 & 7;
    const int axor1 = arow1 & 7;
    const int ac_off = quad >> 1;
    const int krow_base = l7 + (quad & 1) * 8;
    const int bxor = krow_base & 7;
    const int g = lane >> 2;
    const int t2 = lane & 3;

    // ---- Phase 1: load X into A images ----
    load_x_images(smem, X + m0 * EE);

    // ---- Phase 2: q = X @ Wq (two-pass hi/lo) ----
    float acc[2][4][4];
#pragma unroll
    for (int ii = 0; ii < 2; ++ii)
#pragma unroll
        for (int jj = 0; jj < 4; ++jj)
#pragma unroll
            for (int kk = 0; kk < 4; ++kk) acc[ii][jj][kk] = 0.f;
    proj_mma(smem, sb, g_wimg + 0 * 4096, acc);   // Wq (internally syncs)

    __syncthreads();   // all X ldsm done; W slot free

    // ---- Phase 3: copy KtV images into W region; q epilogue (elu, Z, image) ----
    {
        const uint4* src = g_ktvimg + (long long)br * 1024;
#pragma unroll
        for (int it = 0; it < 2; ++it) {
            int i = tid + it * 256;
            int h = i >> 7;
            int d = (i >> 2) & 31;
            int cc = i & 3;
            int off = (h * 32 + d) * 256 + (((h * 4 + cc) ^ (d & 7)) << 4);
            *(uint4*)(smem + SOFF_WHI2 + off) = src[i];
            *(uint4*)(smem + SOFF_WLO2 + off) = src[512 + i];
        }
    }
    float zr[2][2];
    {
        float ks[4][2];
#pragma unroll
        for (int nt = 0; nt < 4; ++nt) {
            float2 kk = *(const float2*)(g_ksum_final + br * 128 + wc0 + nt * 8 + t2 * 2);
            ks[nt][0] = kk.x;
            ks[nt][1] = kk.y;
        }
#pragma unroll
        for (int mt = 0; mt < 2; ++mt) {
            int r0 = wr0 + mt * 16 + g;
            int r1 = r0 + 8;
            float d0 = 0.f, d1 = 0.f;
#pragma unroll
            for (int nt = 0; nt < 4; ++nt) {
                int col = wc0 + nt * 8 + t2 * 2;
                float2 bb = *(const float2*)(bq + col);
                float v0 = elu1(acc[mt][nt][0] + bb.x);
                float v1 = elu1(acc[mt][nt][1] + bb.y);
                float v2 = elu1(acc[mt][nt][2] + bb.x);
                float v3 = elu1(acc[mt][nt][3] + bb.y);
                d0 = fmaf(v0, ks[nt][0], fmaf(v1, ks[nt][1], d0));
                d1 = fmaf(v2, ks[nt][0], fmaf(v3, ks[nt][1], d1));
                int ch = col >> 3;
                int ib = (col & 7) * 2;
                u32 hi0, lo0, hi1, lo1;
                cvt2(v0, v1, hi0, lo0);
                cvt2(v2, v3, hi1, lo1);
                int off0 = r0 * 256 + ((ch ^ (r0 & 7)) << 4) + ib;
                int off1 = r1 * 256 + ((ch ^ (r1 & 7)) << 4) + ib;
                *(u32*)(smem + SOFF_AHI + off0) = hi0;
                *(u32*)(smem + SOFF_ALO + off0) = lo0;
                *(u32*)(smem + SOFF_AHI + off1) = hi1;
                *(u32*)(smem + SOFF_ALO + off1) = lo1;
            }
            d0 += __shfl_xor_sync(0xffffffffu, d0, 1);
            d0 += __shfl_xor_sync(0xffffffffu, d0, 2);
            d1 += __shfl_xor_sync(0xffffffffu, d1, 1);
            d1 += __shfl_xor_sync(0xffffffffu, d1, 2);
            zr[mt][0] = 1.0f / (d0 + 1e-6f);
            zr[mt][1] = 1.0f / (d1 + 1e-6f);
        }
    }
    __syncthreads();   // q images + KtV images visible

    // ---- Phase 4: t = q @ KtV (per-head K=32), Z-scale, overwrite A in place ----
    {
#pragma unroll
        for (int ii = 0; ii < 2; ++ii)
#pragma unroll
            for (int jj = 0; jj < 4; ++jj)
#pragma unroll
                for (int kk = 0; kk < 4; ++kk) acc[ii][jj][kk] = 0.f;

#pragma unroll
        for (int ks = 0; ks < 2; ++ks) {
            u32 ah0[4], ah1[4], al0[4], al1[4];
            {
                int chA = hh * 4 + ks * 2 + ac_off;
                int offA0 = arow0 * 256 + ((chA ^ axor0) << 4);
                int offA1 = arow1 * 256 + ((chA ^ axor1) << 4);
                ldsm4(sb + SOFF_AHI + offA0, ah0[0], ah0[1], ah0[2], ah0[3]);
                ldsm4(sb + SOFF_ALO + offA0, al0[0], al0[1], al0[2], al0[3]);
                ldsm4(sb + SOFF_AHI + offA1, ah1[0], ah1[1], ah1[2], ah1[3]);
                ldsm4(sb + SOFF_ALO + offA1, al1[0], al1[1], al1[2], al1[3]);
            }
#pragma unroll
            for (int p = 0; p < 2; ++p) {
                int chB = hh * 4 + p * 2 + (quad >> 1);
                int brow = hh * 32 + ks * 16 + krow_base;
                int offB = brow * 256 + ((chB ^ bxor) << 4);
                u32 wb0, wb1, wb2, wb3;
                ldsm4t(sb + SOFF_WHI2 + offB, wb0, wb1, wb2, wb3);
                mma_bf16(acc[0][2 * p],     ah0, wb0, wb1);
                mma_bf16(acc[0][2 * p + 1], ah0, wb2, wb3);
                mma_bf16(acc[1][2 * p],     ah1, wb0, wb1);
                mma_bf16(acc[1][2 * p + 1], ah1, wb2, wb3);
                mma_bf16(acc[0][2 * p],     al0, wb0, wb1);
                mma_bf16(acc[0][2 * p + 1], al0, wb2, wb3);
                mma_bf16(acc[1][2 * p],     al1, wb0, wb1);
                mma_bf16(acc[1][2 * p + 1], al1, wb2, wb3);
                ldsm4t(sb + SOFF_WLO2 + offB, wb0, wb1, wb2, wb3);
                mma_bf16(acc[0][2 * p],     ah0, wb0, wb1);
                mma_bf16(acc[0][2 * p + 1], ah0, wb2, wb3);
                mma_bf16(acc[1][2 * p],     ah1, wb0, wb1);
                mma_bf16(acc[1][2 * p + 1], ah1, wb2, wb3);
            }
        }

        // Z-scale + write t back into the A image (warp-local chunks; no sync)
#pragma unroll
        for (int mt = 0; mt < 2; ++mt) {
            int r0 = wr0 + mt * 16 + g;
            int r1 = r0 + 8;
            float z0 = zr[mt][0];
            float z1 = zr[mt][1];
#pragma unroll
            for (int nt = 0; nt < 4; ++nt) {
                int col = wc0 + nt * 8 + t2 * 2;
                int ch = col >> 3;
                int ib = (col & 7) * 2;
                u32 hi0, lo0, hi1, lo1;
                cvt2(acc[mt][nt][0] * z0, acc[mt][nt][1] * z0, hi0, lo0);
                cvt2(acc[mt][nt][2] * z1, acc[mt][nt][3] * z1, hi1, lo1);
                int off0 = r0 * 256 + ((ch ^ (r0 & 7)) << 4) + ib;
                int off1 = r1 * 256 + ((ch ^ (r1 & 7)) << 4) + ib;
                *(u32*)(smem + SOFF_AHI + off0) = hi0;
                *(u32*)(smem + SOFF_ALO + off0) = lo0;
                *(u32*)(smem + SOFF_AHI + off1) = hi1;
                *(u32*)(smem + SOFF_ALO + off1) = lo1;
            }
        }
    }
    __syncthreads();   // t images visible; KtV reads done

    // ---- Phase 5: copy Wo images over KtV region ----
    {
        const uint4* wsrc = g_wimg + 3 * 4096;
#pragma unroll
        for (int it = 0; it < 8; ++it) {
            int i = tid + it * 256;
            *(uint4*)(smem + SOFF_WHI2 + i * 16) = wsrc[i];
            *(uint4*)(smem + SOFF_WLO2 + i * 16) = wsrc[2048 + i];
        }
    }
    __syncthreads();

    // ---- Phase 6: out = t @ Wo + bo (K=128) ----
#pragma unroll
    for (int ii = 0; ii < 2; ++ii)
#pragma unroll
        for (int jj = 0; jj < 4; ++jj)
#pragma unroll
            for (int kk = 0; kk < 4; ++kk) acc[ii][jj][kk] = 0.f;

#pragma unroll 2
    for (int ks = 0; ks < 8; ++ks) {
        u32 ah0[4], ah1[4], al0[4], al1[4];
        {
            int offA0 = arow0 * 256 + (((ks * 2 + ac_off) ^ axor0) << 4);
            int offA1 = arow1 * 256 + (((ks * 2 + ac_off) ^ axor1) << 4);
            ldsm4(sb + SOFF_AHI + offA0, ah0[0], ah0[1], ah0[2], ah0[3]);
            ldsm4(sb + SOFF_ALO + offA0, al0[0], al0[1], al0[2], al0[3]);
            ldsm4(sb + SOFF_AHI + offA1, ah1[0], ah1[1], ah1[2], ah1[3]);
            ldsm4(sb + SOFF_ALO + offA1, al1[0], al1[1], al1[2], al1[3]);
        }
#pragma unroll
        for (int p = 0; p < 2; ++p) {
            int chB = (wc0 >> 3) + p * 2 + (quad >> 1);
            int offB = (ks * 16 + krow_base) * 256 + ((chB ^ bxor) << 4);
            u32 wb0, wb1, wb2, wb3;
            ldsm4t(sb + SOFF_WHI2 + offB, wb0, wb1, wb2, wb3);
            mma_bf16(acc[0][2 * p],     ah0, wb0, wb1);
            mma_bf16(acc[0][2 * p + 1], ah0, wb2, wb3);
            mma_bf16(acc[1][2 * p],     ah1, wb0, wb1);
            mma_bf16(acc[1][2 * p + 1], ah1, wb2, wb3);
            mma_bf16(acc[0][2 * p],     al0, wb0, wb1);
            mma_bf16(acc[0][2 * p + 1], al0, wb2, wb3);
            mma_bf16(acc[1][2 * p],     al1, wb0, wb1);
            mma_bf16(acc[1][2 * p + 1], al1, wb2, wb3);
            ldsm4t(sb + SOFF_WLO2 + offB, wb0, wb1, wb2, wb3);
            mma_bf16(acc[0][2 * p],     ah0, wb0, wb1);
            mma_bf16(acc[0][2 * p + 1], ah0, wb2, wb3);
            mma_bf16(acc[1][2 * p],     ah1, wb0, wb1);
            mma_bf16(acc[1][2 * p + 1], ah1, wb2, wb3);
        }
    }

#pragma unroll
    for (int mt = 0; mt < 2; ++mt) {
#pragma unroll
        for (int nt = 0; nt < 4; ++nt) {
            int col = wc0 + nt * 8 + t2 * 2;
            float2 bb = *(const float2*)(bo + col);
            long long r0g = m0 + wr0 + mt * 16 + g;
            float v0 = acc[mt][nt][0] + bb.x;
            float v1 = acc[mt][nt][1] + bb.y;
            float v2 = acc[mt][nt][2] + bb.x;
            float v3 = acc[mt][nt][3] + bb.y;
            *(float2*)(out + r0g * EE + col)       = make_float2(v0, v1);
            *(float2*)(out + (r0g + 8) * EE + col) = make_float2(v2, v3);
        }
    }
}

// ---------------------------------------------------------------------------
extern "C" void kernel_launch(void* const* d_in, const int* in_sizes, int n_in,
                              void* d_out, int out_size)
{
    const float* X  = (const float*)d_in[0];
    const float* Wq = (const float*)d_in[1];
    const float* bq = (const float*)d_in[2];
    const float* Wk = (const float*)d_in[3];
    const float* bk = (const float*)d_in[4];
    const float* Wv = (const float*)d_in[5];
    const float* bv = (const float*)d_in[6];
    const float* Wo = (const float*)d_in[7];
    const float* bo = (const float*)d_in[8];
    float* out = (float*)d_out;

    cudaFuncSetAttribute(fused_kv_ktv_kernel, cudaFuncAttributeMaxDynamicSharedMemorySize, SMEM_FUSED);
    cudaFuncSetAttribute(tout_kernel, cudaFuncAttributeMaxDynamicSharedMemorySize, SMEM_TOUT);

    prep_w_kernel<<<4, 256>>>(Wq, Wk, Wv, Wo);
    fused_kv_ktv_kernel<<<NTILES, 256, SMEM_FUSED>>>(X, bk, bv);
    ktv_reduce_kernel<<<NKV, 512>>>();
    tout_kernel<<<NTILES, 256, SMEM_TOUT>>>(X, bq, bo, out);
}